// round 15
// baseline (speedup 1.0000x reference)
#include <cuda_runtime.h>

// HCEN forward, two kernels:
//  K1: x stream (proven shape), atomicAdd batch sums into g_m (no reduce).
//      x loads use ld.global.cs (evict-first streaming).
//  K2: fused GEMM tail with W loaded via ld.global.L2::evict_last.v8.b32
//      (sm_103a requires 256-bit for evict_last) -> W stays L2-resident
//      ACROSS graph replays; steady-state tail runs from L2, not DRAM.

#define BATCH 16
#define SEQ   4096
#define DIM   1024
#define NCHUNK 64
#define SCHUNK (SEQ / NCHUNK)   // 64
#define FB2   256               // tail grid (2 blocks/SM, co-resident)

// Device-global scratch (no allocation allowed).
__device__ float g_m[BATCH * DIM];       // 64 KB (sum accumulator; K2 re-zeroes)
__device__ float g_enc[BATCH * DIM];     // 64 KB
__device__ volatile unsigned g_bar[1];   // zero-init; self-resetting
__device__ unsigned g_exit;

// 32-byte load with L2 evict-last priority (pins the line in L2).
__device__ __forceinline__ void ld_el8(const float* p, float4& a, float4& b) {
    unsigned r0, r1, r2, r3, r4, r5, r6, r7;
    asm volatile("ld.global.L2::evict_last.v8.b32 {%0,%1,%2,%3,%4,%5,%6,%7}, [%8];"
                 : "=r"(r0), "=r"(r1), "=r"(r2), "=r"(r3),
                   "=r"(r4), "=r"(r5), "=r"(r6), "=r"(r7)
                 : "l"(p));
    a.x = __uint_as_float(r0); a.y = __uint_as_float(r1);
    a.z = __uint_as_float(r2); a.w = __uint_as_float(r3);
    b.x = __uint_as_float(r4); b.y = __uint_as_float(r5);
    b.z = __uint_as_float(r6); b.w = __uint_as_float(r7);
}

// ---------------------------------------------------------------------------
// K1: grid (16, 64), block 256. Block (b,c) sums rows [c*64, c*64+64) of
// batch b; thread t owns float4 column t. __ldcs: read-once, evict-first.
// ---------------------------------------------------------------------------
__global__ void mean_partial_kernel(const float* __restrict__ x) {
    const int b = blockIdx.x;
    const int c = blockIdx.y;
    const int t = threadIdx.x;

    const float4* __restrict__ x4 =
        reinterpret_cast<const float4*>(x + ((size_t)b * SEQ + (size_t)c * SCHUNK) * DIM);

    float4 acc = make_float4(0.f, 0.f, 0.f, 0.f);
#pragma unroll 16
    for (int s = 0; s < SCHUNK; s++) {
        float4 v = __ldcs(&x4[(size_t)s * (DIM / 4) + t]);
        acc.x += v.x; acc.y += v.y; acc.z += v.z; acc.w += v.w;
    }

    float* gm = g_m + (size_t)b * DIM + (size_t)t * 4;
    atomicAdd(gm + 0, acc.x);
    atomicAdd(gm + 1, acc.y);
    atomicAdd(gm + 2, acc.z);
    atomicAdd(gm + 3, acc.w);
}

// ---------------------------------------------------------------------------
// Grid barrier across K2's 256 co-resident blocks.
// ---------------------------------------------------------------------------
__device__ __forceinline__ void grid_barrier(int which) {
    __syncthreads();
    if (threadIdx.x == 0) {
        __threadfence();
        atomicAdd((unsigned*)&g_bar[which], 1u);
        while (g_bar[which] < FB2) { }
        __threadfence();
    }
    __syncthreads();
}

// ---------------------------------------------------------------------------
// K2: fused GEMM tail. grid 256, block 256 (8 warps), 2 CTAs/SM.
// Block bid: h-group hg = bid>>1 (8 h rows), batch half = bid&1 (8 batches).
// Warp w owns h = hg*8 + w for its half.
// W register layout: lane owns 4 contiguous 8-float chunks -- chunk c covers
// floats [c*256 + lane*8, +8), matching the v8.b32 evict_last loads.
// ---------------------------------------------------------------------------
__global__ void __launch_bounds__(256, 2)
fused_tail_kernel(const float* __restrict__ Wenc,
                  const float* __restrict__ benc,
                  const float* __restrict__ Wout,
                  const float* __restrict__ bout,
                  float* __restrict__ dout) {
    __shared__ float4 smA[8 * (DIM / 4)];   // 32 KB: 8 batches x full K

    const int t    = threadIdx.x;
    const int w    = t >> 5;
    const int lane = t & 31;
    const int bid  = blockIdx.x;
    const int hg   = bid >> 1;
    const int half = bid & 1;
    const int h    = hg * 8 + w;

    // ---- Front-loaded W burst into registers (evict_last pins L2). ----
    const float* We = Wenc + (size_t)h * DIM;
    const float* Wo = Wout + (size_t)h * DIM;
    float4 wrA[4], wrB[4], woA[4], woB[4];
#pragma unroll
    for (int c = 0; c < 4; c++)
        ld_el8(We + c * 256 + lane * 8, wrA[c], wrB[c]);
#pragma unroll
    for (int c = 0; c < 4; c++)
        ld_el8(Wo + c * 256 + lane * 8, woA[c], woB[c]);

    // ---- (G1) enc = (g_m / SEQ) @ Wenc^T + benc, this block's 8 batches. ----
    {
        const float4* __restrict__ M4 = reinterpret_cast<const float4*>(g_m);
        const float inv = 1.0f / (float)SEQ;
#pragma unroll
        for (int i = 0; i < 8; i++) {
            float4 v = M4[(size_t)half * 2048 + t + i * 256];
            v.x *= inv; v.y *= inv; v.z *= inv; v.w *= inv;
            smA[t + i * 256] = v;
        }
        __syncthreads();

        float acc[8] = {0.f, 0.f, 0.f, 0.f, 0.f, 0.f, 0.f, 0.f};
#pragma unroll
        for (int c = 0; c < 4; c++) {
            const int j = c * 64 + lane * 2;
#pragma unroll
            for (int b = 0; b < 8; b++) {
                const float4 a0 = smA[b * 256 + j];
                const float4 a1 = smA[b * 256 + j + 1];
                acc[b] += wrA[c].x * a0.x + wrA[c].y * a0.y + wrA[c].z * a0.z + wrA[c].w * a0.w
                        + wrB[c].x * a1.x + wrB[c].y * a1.y + wrB[c].z * a1.z + wrB[c].w * a1.w;
            }
        }
#pragma unroll
        for (int off = 16; off > 0; off >>= 1)
#pragma unroll
            for (int b = 0; b < 8; b++)
                acc[b] += __shfl_down_sync(0xffffffffu, acc[b], off);
        if (lane == 0) {
            const float bv = benc[h];
#pragma unroll
            for (int b = 0; b < 8; b++)
                g_enc[(size_t)(half * 8 + b) * DIM + h] = acc[b] + bv;
        }
        __syncthreads();
    }

    grid_barrier(0);

    // ---- Reset own g_m slice for next graph replay (64 floats/block). ----
    if (t < 64)
        g_m[(size_t)bid * 64 + t] = 0.f;

    // ---- (G2) out = enc @ Wout^T + bout, this block's 8 batches. ----
    {
        const float4* __restrict__ E4 = reinterpret_cast<const float4*>(g_enc);
#pragma unroll
        for (int i = 0; i < 8; i++)
            smA[t + i * 256] = E4[(size_t)half * 2048 + t + i * 256];
        __syncthreads();

        float acc[8] = {0.f, 0.f, 0.f, 0.f, 0.f, 0.f, 0.f, 0.f};
#pragma unroll
        for (int c = 0; c < 4; c++) {
            const int j = c * 64 + lane * 2;
#pragma unroll
            for (int b = 0; b < 8; b++) {
                const float4 a0 = smA[b * 256 + j];
                const float4 a1 = smA[b * 256 + j + 1];
                acc[b] += woA[c].x * a0.x + woA[c].y * a0.y + woA[c].z * a0.z + woA[c].w * a0.w
                        + woB[c].x * a1.x + woB[c].y * a1.y + woB[c].z * a1.z + woB[c].w * a1.w;
            }
        }
#pragma unroll
        for (int off = 16; off > 0; off >>= 1)
#pragma unroll
            for (int b = 0; b < 8; b++)
                acc[b] += __shfl_down_sync(0xffffffffu, acc[b], off);
        if (lane == 0) {
            const float bv = bout[h];
#pragma unroll
            for (int b = 0; b < 8; b++)
                dout[(size_t)(half * 8 + b) * DIM + h] = acc[b] + bv;
        }
    }

    // ---- reset counters for next graph replay (last block out). ----
    __syncthreads();
    if (t == 0) {
        unsigned old = atomicAdd(&g_exit, 1u);
        if (old == FB2 - 1) {
            g_bar[0] = 0;
            __threadfence();
            g_exit = 0;
        }
    }
}

extern "C" void kernel_launch(void* const* d_in, const int* in_sizes, int n_in,
                              void* d_out, int out_size) {
    const float* x     = (const float*)d_in[0];
    const float* W_enc = (const float*)d_in[1];
    const float* b_enc = (const float*)d_in[2];
    const float* W_out = (const float*)d_in[3];
    const float* b_out = (const float*)d_in[4];
    float* out = (float*)d_out;

    (void)in_sizes; (void)n_in; (void)out_size;

    mean_partial_kernel<<<dim3(BATCH, NCHUNK), 256>>>(x);
    fused_tail_kernel<<<FB2, 256>>>(W_enc, b_enc, W_out, b_out, out);
}

// round 16
// speedup vs baseline: 1.0097x; 1.0097x over previous
#include <cuda_runtime.h>

// HCEN forward, two kernels:
//  K1: x stream (proven shape), atomicAdd batch sums into g_m (no reduce).
//      x loads use ld.global.cs (evict-first streaming).
//  K2: fused GEMM tail with W loaded via ld.global.L2::evict_last.v8.b32
//      (sm_103a requires 256-bit for evict_last) -> W stays L2-resident
//      ACROSS graph replays; steady-state tail runs from L2, not DRAM.

#define BATCH 16
#define SEQ   4096
#define DIM   1024
#define NCHUNK 64
#define SCHUNK (SEQ / NCHUNK)   // 64
#define FB2   256               // tail grid (2 blocks/SM, co-resident)

// Device-global scratch (no allocation allowed).
__device__ float g_m[BATCH * DIM];       // 64 KB (sum accumulator; K2 re-zeroes)
__device__ float g_enc[BATCH * DIM];     // 64 KB
__device__ volatile unsigned g_bar[1];   // zero-init; self-resetting
__device__ unsigned g_exit;

// 32-byte load with L2 evict-last priority (pins the line in L2).
__device__ __forceinline__ void ld_el8(const float* p, float4& a, float4& b) {
    unsigned r0, r1, r2, r3, r4, r5, r6, r7;
    asm volatile("ld.global.L2::evict_last.v8.b32 {%0,%1,%2,%3,%4,%5,%6,%7}, [%8];"
                 : "=r"(r0), "=r"(r1), "=r"(r2), "=r"(r3),
                   "=r"(r4), "=r"(r5), "=r"(r6), "=r"(r7)
                 : "l"(p));
    a.x = __uint_as_float(r0); a.y = __uint_as_float(r1);
    a.z = __uint_as_float(r2); a.w = __uint_as_float(r3);
    b.x = __uint_as_float(r4); b.y = __uint_as_float(r5);
    b.z = __uint_as_float(r6); b.w = __uint_as_float(r7);
}

// ---------------------------------------------------------------------------
// K1: grid (16, 64), block 256. Block (b,c) sums rows [c*64, c*64+64) of
// batch b; thread t owns float4 column t. __ldcs: read-once, evict-first.
// ---------------------------------------------------------------------------
__global__ void mean_partial_kernel(const float* __restrict__ x) {
    const int b = blockIdx.x;
    const int c = blockIdx.y;
    const int t = threadIdx.x;

    const float4* __restrict__ x4 =
        reinterpret_cast<const float4*>(x + ((size_t)b * SEQ + (size_t)c * SCHUNK) * DIM);

    float4 acc = make_float4(0.f, 0.f, 0.f, 0.f);
#pragma unroll 16
    for (int s = 0; s < SCHUNK; s++) {
        float4 v = __ldcs(&x4[(size_t)s * (DIM / 4) + t]);
        acc.x += v.x; acc.y += v.y; acc.z += v.z; acc.w += v.w;
    }

    float* gm = g_m + (size_t)b * DIM + (size_t)t * 4;
    atomicAdd(gm + 0, acc.x);
    atomicAdd(gm + 1, acc.y);
    atomicAdd(gm + 2, acc.z);
    atomicAdd(gm + 3, acc.w);
}

// ---------------------------------------------------------------------------
// Grid barrier across K2's 256 co-resident blocks.
// ---------------------------------------------------------------------------
__device__ __forceinline__ void grid_barrier(int which) {
    __syncthreads();
    if (threadIdx.x == 0) {
        __threadfence();
        atomicAdd((unsigned*)&g_bar[which], 1u);
        while (g_bar[which] < FB2) { }
        __threadfence();
    }
    __syncthreads();
}

// ---------------------------------------------------------------------------
// K2: fused GEMM tail. grid 256, block 256 (8 warps), 2 CTAs/SM.
// Block bid: h-group hg = bid>>1 (8 h rows), batch half = bid&1 (8 batches).
// Warp w owns h = hg*8 + w for its half.
// W register layout: lane owns 4 contiguous 8-float chunks -- chunk c covers
// floats [c*256 + lane*8, +8), matching the v8.b32 evict_last loads.
// ---------------------------------------------------------------------------
__global__ void __launch_bounds__(256, 2)
fused_tail_kernel(const float* __restrict__ Wenc,
                  const float* __restrict__ benc,
                  const float* __restrict__ Wout,
                  const float* __restrict__ bout,
                  float* __restrict__ dout) {
    __shared__ float4 smA[8 * (DIM / 4)];   // 32 KB: 8 batches x full K

    const int t    = threadIdx.x;
    const int w    = t >> 5;
    const int lane = t & 31;
    const int bid  = blockIdx.x;
    const int hg   = bid >> 1;
    const int half = bid & 1;
    const int h    = hg * 8 + w;

    // ---- Front-loaded W burst into registers (evict_last pins L2). ----
    const float* We = Wenc + (size_t)h * DIM;
    const float* Wo = Wout + (size_t)h * DIM;
    float4 wrA[4], wrB[4], woA[4], woB[4];
#pragma unroll
    for (int c = 0; c < 4; c++)
        ld_el8(We + c * 256 + lane * 8, wrA[c], wrB[c]);
#pragma unroll
    for (int c = 0; c < 4; c++)
        ld_el8(Wo + c * 256 + lane * 8, woA[c], woB[c]);

    // ---- (G1) enc = (g_m / SEQ) @ Wenc^T + benc, this block's 8 batches. ----
    {
        const float4* __restrict__ M4 = reinterpret_cast<const float4*>(g_m);
        const float inv = 1.0f / (float)SEQ;
#pragma unroll
        for (int i = 0; i < 8; i++) {
            float4 v = M4[(size_t)half * 2048 + t + i * 256];
            v.x *= inv; v.y *= inv; v.z *= inv; v.w *= inv;
            smA[t + i * 256] = v;
        }
        __syncthreads();

        float acc[8] = {0.f, 0.f, 0.f, 0.f, 0.f, 0.f, 0.f, 0.f};
#pragma unroll
        for (int c = 0; c < 4; c++) {
            const int j = c * 64 + lane * 2;
#pragma unroll
            for (int b = 0; b < 8; b++) {
                const float4 a0 = smA[b * 256 + j];
                const float4 a1 = smA[b * 256 + j + 1];
                acc[b] += wrA[c].x * a0.x + wrA[c].y * a0.y + wrA[c].z * a0.z + wrA[c].w * a0.w
                        + wrB[c].x * a1.x + wrB[c].y * a1.y + wrB[c].z * a1.z + wrB[c].w * a1.w;
            }
        }
#pragma unroll
        for (int off = 16; off > 0; off >>= 1)
#pragma unroll
            for (int b = 0; b < 8; b++)
                acc[b] += __shfl_down_sync(0xffffffffu, acc[b], off);
        if (lane == 0) {
            const float bv = benc[h];
#pragma unroll
            for (int b = 0; b < 8; b++)
                g_enc[(size_t)(half * 8 + b) * DIM + h] = acc[b] + bv;
        }
        __syncthreads();
    }

    grid_barrier(0);

    // ---- Reset own g_m slice for next graph replay (64 floats/block). ----
    if (t < 64)
        g_m[(size_t)bid * 64 + t] = 0.f;

    // ---- (G2) out = enc @ Wout^T + bout, this block's 8 batches. ----
    {
        const float4* __restrict__ E4 = reinterpret_cast<const float4*>(g_enc);
#pragma unroll
        for (int i = 0; i < 8; i++)
            smA[t + i * 256] = E4[(size_t)half * 2048 + t + i * 256];
        __syncthreads();

        float acc[8] = {0.f, 0.f, 0.f, 0.f, 0.f, 0.f, 0.f, 0.f};
#pragma unroll
        for (int c = 0; c < 4; c++) {
            const int j = c * 64 + lane * 2;
#pragma unroll
            for (int b = 0; b < 8; b++) {
                const float4 a0 = smA[b * 256 + j];
                const float4 a1 = smA[b * 256 + j + 1];
                acc[b] += woA[c].x * a0.x + woA[c].y * a0.y + woA[c].z * a0.z + woA[c].w * a0.w
                        + woB[c].x * a1.x + woB[c].y * a1.y + woB[c].z * a1.z + woB[c].w * a1.w;
            }
        }
#pragma unroll
        for (int off = 16; off > 0; off >>= 1)
#pragma unroll
            for (int b = 0; b < 8; b++)
                acc[b] += __shfl_down_sync(0xffffffffu, acc[b], off);
        if (lane == 0) {
            const float bv = bout[h];
#pragma unroll
            for (int b = 0; b < 8; b++)
                dout[(size_t)(half * 8 + b) * DIM + h] = acc[b] + bv;
        }
    }

    // ---- reset counters for next graph replay (last block out). ----
    __syncthreads();
    if (t == 0) {
        unsigned old = atomicAdd(&g_exit, 1u);
        if (old == FB2 - 1) {
            g_bar[0] = 0;
            __threadfence();
            g_exit = 0;
        }
    }
}

extern "C" void kernel_launch(void* const* d_in, const int* in_sizes, int n_in,
                              void* d_out, int out_size) {
    const float* x     = (const float*)d_in[0];
    const float* W_enc = (const float*)d_in[1];
    const float* b_enc = (const float*)d_in[2];
    const float* W_out = (const float*)d_in[3];
    const float* b_out = (const float*)d_in[4];
    float* out = (float*)d_out;

    (void)in_sizes; (void)n_in; (void)out_size;

    mean_partial_kernel<<<dim3(BATCH, NCHUNK), 256>>>(x);
    fused_tail_kernel<<<FB2, 256>>>(W_enc, b_enc, W_out, b_out, out);
}